// round 9
// baseline (speedup 1.0000x reference)
#include <cuda_runtime.h>
#include <cuda_fp16.h>

#define D 128
#define DV 32            // float4 per row
#define BM 64            // gemm rows per block
#define LDS_X 132        // padded smem stride (floats), 16B-aligned rows
#define MAXN 100352
#define MAXE 1700000

// ---------------- scratch (device globals: no allocation allowed) -------------
__device__ unsigned g_h16[MAXN * 64];   // half2-packed pre-scaled hidden
__device__ float g_x[MAXN * D];
__device__ float g_y[MAXN * D];
__device__ float g_dinv[MAXN];
__device__ int   g_deg[MAXN];
__device__ int   g_rowstart[MAXN + 1];
__device__ int   g_cursor[MAXN];
__device__ int   g_csr_src[MAXE];
__device__ int   g_part[64];
__device__ float g_wt[5 * D * D];       // transposed weights (col-major W)

// ---------------- packed f32x2 helpers (Blackwell FFMA2 path) ----------------
__device__ __forceinline__ void unpack2(unsigned long long v, float& a, float& b) {
    asm("mov.b64 {%0, %1}, %2;" : "=f"(a), "=f"(b) : "l"(v));
}
__device__ __forceinline__ unsigned long long ffma2(unsigned long long a,
                                                    unsigned long long b,
                                                    unsigned long long c) {
    unsigned long long d;
    asm("fma.rn.f32x2 %0, %1, %2, %3;" : "=l"(d) : "l"(a), "l"(b), "l"(c));
    return d;
}

// ---------------- degree / normalization ------------------------------------
__global__ void zero_deg_kernel(int n) {
    int i = blockIdx.x * blockDim.x + threadIdx.x;
    if (i < n) g_deg[i] = 0;
}

__global__ void count_deg_kernel(const int* __restrict__ dst, int E) {
    int e = blockIdx.x * blockDim.x + threadIdx.x;
    if (e < E) atomicAdd(&g_deg[dst[e]], 1);
}

__global__ void dinv_kernel(int n) {
    int i = blockIdx.x * blockDim.x + threadIdx.x;
    if (i < n) g_dinv[i] = rsqrtf((float)(g_deg[i] + 1));
}

// ---- multi-block scan: pass 1, per-block (4096 elems) partial sums ----------
__global__ void scan_part_kernel(int n) {
    int base = blockIdx.x * 4096;
    int sum = 0;
    for (int i = threadIdx.x; i < 4096; i += 256) {
        int idx = base + i;
        if (idx < n) sum += g_deg[idx];
    }
    #pragma unroll
    for (int o = 16; o > 0; o >>= 1) sum += __shfl_xor_sync(0xffffffffu, sum, o);
    __shared__ int ws[8];
    if ((threadIdx.x & 31) == 0) ws[threadIdx.x >> 5] = sum;
    __syncthreads();
    if (threadIdx.x == 0) {
        int t = 0;
        #pragma unroll
        for (int w = 0; w < 8; ++w) t += ws[w];
        g_part[blockIdx.x] = t;
    }
}

// ---- pass 2: per-block exclusive scan of its 4096 chunk + global offset -----
__global__ void scan_final_kernel(int n, int nblocks) {
    __shared__ int s_off;
    __shared__ int warp_sums[32];
    int tid = threadIdx.x;                  // 1024 threads
    int base = blockIdx.x * 4096;
    if (tid == 0) {
        int off = 0;
        for (int b = 0; b < blockIdx.x; ++b) off += g_part[b];
        s_off = off;
        if (blockIdx.x == 0) {
            int tot = 0;
            for (int b = 0; b < nblocks; ++b) tot += g_part[b];
            g_rowstart[n] = tot;
        }
    }
    __syncthreads();

    int i0 = base + tid * 4;
    int v[4];
    int s = 0;
    #pragma unroll
    for (int k = 0; k < 4; ++k) {
        int idx = i0 + k;
        v[k] = (idx < n) ? g_deg[idx] : 0;
        s += v[k];
    }
    int lane = tid & 31, wid = tid >> 5;
    int x = s;
    #pragma unroll
    for (int o = 1; o < 32; o <<= 1) {
        int y = __shfl_up_sync(0xffffffffu, x, o);
        if (lane >= o) x += y;
    }
    if (lane == 31) warp_sums[wid] = x;
    __syncthreads();
    if (wid == 0) {
        int w = warp_sums[lane];
        #pragma unroll
        for (int o = 1; o < 32; o <<= 1) {
            int y = __shfl_up_sync(0xffffffffu, w, o);
            if (lane >= o) w += y;
        }
        warp_sums[lane] = w;
    }
    __syncthreads();
    int excl = x - s + ((wid > 0) ? warp_sums[wid - 1] : 0) + s_off;
    #pragma unroll
    for (int k = 0; k < 4; ++k) {
        int idx = i0 + k;
        if (idx < n) {
            g_rowstart[idx] = excl;
            g_cursor[idx]   = excl;
            excl += v[k];
        }
    }
}

__global__ void fill_kernel(const int* __restrict__ src, const int* __restrict__ dst, int E) {
    int e = blockIdx.x * blockDim.x + threadIdx.x;
    if (e >= E) return;
    int u = src[e], v = dst[e];
    int slot = atomicAdd(&g_cursor[v], 1);
    g_csr_src[slot] = u;
}

// ---------------- weight transpose: g_wt[z][n][k] = W_z[k][n] ----------------
__global__ void transpose_w_kernel(const float* __restrict__ W1, const float* __restrict__ W2,
                                   const float* __restrict__ W3, const float* __restrict__ W4,
                                   const float* __restrict__ W5) {
    const float* srcs[5] = {W1, W2, W3, W4, W5};
    __shared__ float t[32][33];
    int z = blockIdx.z;
    const float* S = srcs[z];
    float* Dst = g_wt + z * D * D;
    int bx = blockIdx.x * 32;   // n tile
    int by = blockIdx.y * 32;   // k tile
    int x = bx + threadIdx.x;
    #pragma unroll
    for (int j = 0; j < 32; j += 8)
        t[threadIdx.y + j][threadIdx.x] = S[(by + threadIdx.y + j) * D + x];
    __syncthreads();
    x = by + threadIdx.x;       // now k
    #pragma unroll
    for (int j = 0; j < 32; j += 8)
        Dst[(bx + threadIdx.y + j) * D + x] = t[threadIdx.x][threadIdx.y + j];
}

// ---------------- GEMM: out = X @ W, k-pair packed FFMA2, zero-mov mainloop --
// Wt = transposed weight [n][k]. Thread owns rows ty*8..+7, cols {tx,tx+32,tx+64,tx+96}.
// f32x2 lanes hold (even-k, odd-k) partial sums; summed at the end.
// epi: 1 = relu(acc+bias); 2 = acc+bias+add[row]; 3 = half2(dinv[row]*acc) -> out16
__global__ void gemm_kernel(const float* __restrict__ X, const float* __restrict__ Wt,
                            const float* __restrict__ bias, const float* __restrict__ add,
                            float* __restrict__ out, unsigned* __restrict__ out16,
                            int M, int epi) {
    extern __shared__ float sm[];
    float* Wts = sm;                 // 128 x LDS_X  (Wt rows: n, cols: k)
    float* Xs  = sm + D * LDS_X;     // BM x LDS_X   (X rows, k contiguous; reused as Obuf)
    int row0 = blockIdx.x * BM;
    int tid = threadIdx.x;
    int tx = tid & 31;
    int ty = tid >> 5;

    // stage Wt (128 x 128) into padded smem, coalesced float4
    const float4* Wt4 = (const float4*)Wt;
    for (int i = tid; i < D * DV; i += 256) {
        int r = i >> 5, c4 = i & 31;
        *(float4*)(Wts + r * LDS_X + c4 * 4) = Wt4[r * DV + c4];
    }
    // stage X tile (guard rows)
    const float4* X4 = (const float4*)X;
    for (int i = tid; i < BM * DV; i += 256) {
        int r = i >> 5, c4 = i & 31;
        int gr = row0 + r;
        float4 v = make_float4(0.f, 0.f, 0.f, 0.f);
        if (gr < M) v = X4[gr * DV + c4];
        *(float4*)(Xs + r * LDS_X + c4 * 4) = v;
    }
    __syncthreads();

    unsigned long long acc2[8][4];
    #pragma unroll
    for (int r = 0; r < 8; ++r)
        #pragma unroll
        for (int c = 0; c < 4; ++c) acc2[r][c] = 0ull;

    const float* Xrow = Xs + (ty * 8) * LDS_X;
    const float* Wrow = Wts + tx * LDS_X;

    #pragma unroll 4
    for (int k = 0; k < D; k += 2) {
        unsigned long long wc[4];
        #pragma unroll
        for (int c = 0; c < 4; ++c)
            wc[c] = *(const unsigned long long*)(Wrow + (32 * c) * LDS_X + k);
        #pragma unroll
        for (int r = 0; r < 8; ++r) {
            unsigned long long xr = *(const unsigned long long*)(Xrow + r * LDS_X + k);
            acc2[r][0] = ffma2(xr, wc[0], acc2[r][0]);
            acc2[r][1] = ffma2(xr, wc[1], acc2[r][1]);
            acc2[r][2] = ffma2(xr, wc[2], acc2[r][2]);
            acc2[r][3] = ffma2(xr, wc[3], acc2[r][3]);
        }
    }

    // stage results into Xs (own rows only -> no cross-warp hazard before sync)
    #pragma unroll
    for (int r = 0; r < 8; ++r) {
        float* row = Xs + (ty * 8 + r) * LDS_X;
        #pragma unroll
        for (int c = 0; c < 4; ++c) {
            float lo, hi;
            unpack2(acc2[r][c], lo, hi);
            row[tx + 32 * c] = lo + hi;
        }
    }
    __syncthreads();

    // epilogue: coalesced float4 over staged tile
    if (epi == 3) {
        for (int i = tid; i < BM * DV; i += 256) {
            int r = i >> 5, c4 = i & 31;
            int gr = row0 + r;
            if (gr >= M) continue;
            float s = g_dinv[gr];
            float4 o = *(float4*)(Xs + r * LDS_X + c4 * 4);
            __half2 h0 = __floats2half2_rn(o.x * s, o.y * s);
            __half2 h1 = __floats2half2_rn(o.z * s, o.w * s);
            uint2 pk = make_uint2(*(unsigned*)&h0, *(unsigned*)&h1);
            *(uint2*)(out16 + gr * 64 + 2 * c4) = pk;
        }
        return;
    }

    const float4* add4 = (const float4*)add;
    float4* out4 = (float4*)out;
    for (int i = tid; i < BM * DV; i += 256) {
        int r = i >> 5, c4 = i & 31;
        int gr = row0 + r;
        if (gr >= M) continue;
        float4 o = *(float4*)(Xs + r * LDS_X + c4 * 4);
        float4 b = ((const float4*)bias)[c4];
        o.x += b.x; o.y += b.y; o.z += b.z; o.w += b.w;
        if (epi == 1) {
            o.x = fmaxf(o.x, 0.f); o.y = fmaxf(o.y, 0.f);
            o.z = fmaxf(o.z, 0.f); o.w = fmaxf(o.w, 0.f);
        } else {
            float4 a = add4[gr * DV + c4];
            o.x += a.x; o.y += a.y; o.z += a.z; o.w += a.w;
        }
        out4[gr * DV + c4] = o;
    }
}

// ---------------- fused aggregation + bias + LayerNorm (+ReLU) ---------------
// warp per node, fp16 pre-scaled payload:
// out[v] = LN( dinv[v] * ( hs[v] + sum_{u->v} hs[u] ) + bias )
__global__ void agg_ln_kernel(const unsigned* __restrict__ h16,
                              const float* __restrict__ bias,
                              const float* __restrict__ gamma, const float* __restrict__ beta,
                              float* __restrict__ out, int N, int doRelu) {
    int gw   = (blockIdx.x * blockDim.x + threadIdx.x) >> 5;
    int lane = threadIdx.x & 31;
    if (gw >= N) return;
    int v = gw;

    uint2 pk = *(const uint2*)(h16 + v * 64 + 2 * lane);
    float2 f0 = __half22float2(*(__half2*)&pk.x);
    float2 f1 = __half22float2(*(__half2*)&pk.y);
    float4 acc = make_float4(f0.x, f0.y, f1.x, f1.y);

    int s = g_rowstart[v];
    int e = g_rowstart[v + 1];
    for (int j = s; j < e; ++j) {
        int u = g_csr_src[j];
        uint2 p = *(const uint2*)(h16 + u * 64 + 2 * lane);
        float2 a = __half22float2(*(__half2*)&p.x);
        float2 b = __half22float2(*(__half2*)&p.y);
        acc.x += a.x; acc.y += a.y; acc.z += b.x; acc.w += b.y;
    }

    float dv = g_dinv[v];
    float4 bv = ((const float4*)bias)[lane];
    acc.x = acc.x * dv + bv.x;
    acc.y = acc.y * dv + bv.y;
    acc.z = acc.z * dv + bv.z;
    acc.w = acc.w * dv + bv.w;

    float sum = acc.x + acc.y + acc.z + acc.w;
    #pragma unroll
    for (int o = 16; o > 0; o >>= 1) sum += __shfl_xor_sync(0xffffffffu, sum, o);
    float mu = sum * (1.0f / 128.0f);

    float cx = acc.x - mu, cy = acc.y - mu, cz = acc.z - mu, cw = acc.w - mu;
    float sq = cx * cx + cy * cy + cz * cz + cw * cw;
    #pragma unroll
    for (int o = 16; o > 0; o >>= 1) sq += __shfl_xor_sync(0xffffffffu, sq, o);
    float rs = rsqrtf(sq * (1.0f / 128.0f) + 1e-5f);

    float4 gv  = ((const float4*)gamma)[lane];
    float4 bev = ((const float4*)beta)[lane];
    float4 o;
    o.x = cx * rs * gv.x + bev.x;
    o.y = cy * rs * gv.y + bev.y;
    o.z = cz * rs * gv.z + bev.z;
    o.w = cw * rs * gv.w + bev.w;
    if (doRelu) {
        o.x = fmaxf(o.x, 0.f); o.y = fmaxf(o.y, 0.f);
        o.z = fmaxf(o.z, 0.f); o.w = fmaxf(o.w, 0.f);
    }
    ((float4*)out)[v * DV + lane] = o;
}

// ---------------- driver -----------------------------------------------------
extern "C" void kernel_launch(void* const* d_in, const int* in_sizes, int n_in,
                              void* d_out, int out_size) {
    const int*   edge_index = (const int*)d_in[0];
    const float* ent = (const float*)d_in[1];
    const float* W1  = (const float*)d_in[2];
    const float* b1  = (const float*)d_in[3];
    const float* g1  = (const float*)d_in[4];
    const float* be1 = (const float*)d_in[5];
    const float* W2  = (const float*)d_in[6];
    const float* b2  = (const float*)d_in[7];
    const float* g2  = (const float*)d_in[8];
    const float* be2 = (const float*)d_in[9];
    const float* W3  = (const float*)d_in[10];
    const float* b3  = (const float*)d_in[11];
    const float* g3  = (const float*)d_in[12];
    const float* be3 = (const float*)d_in[13];
    const float* Wt1 = (const float*)d_in[14];
    const float* bt1 = (const float*)d_in[15];
    const float* Wt2 = (const float*)d_in[16];
    const float* bt2 = (const float*)d_in[17];

    int E = in_sizes[0] / 2;
    int N = in_sizes[1] / D;
    const int* src = edge_index;
    const int* dst = edge_index + E;

    float *px, *py, *pwt;
    unsigned *ph16;
    cudaGetSymbolAddress((void**)&ph16, g_h16);
    cudaGetSymbolAddress((void**)&px, g_x);
    cudaGetSymbolAddress((void**)&py, g_y);
    cudaGetSymbolAddress((void**)&pwt, g_wt);

    const int SMEM = (D + BM) * LDS_X * sizeof(float);   // (128+64)*132*4 = 101376 B
    cudaFuncSetAttribute(gemm_kernel, cudaFuncAttributeMaxDynamicSharedMemorySize, SMEM);

    int nb  = (N + 255) / 256;
    int eb  = (E + 255) / 256;
    int gg  = (N + BM - 1) / BM;
    int ab  = (N * 32 + 255) / 256;
    int sb  = (N + 4095) / 4096;

    // graph preprocessing (CSR by dst) + weight transposes
    zero_deg_kernel<<<nb, 256>>>(N);
    count_deg_kernel<<<eb, 256>>>(dst, E);
    dinv_kernel<<<nb, 256>>>(N);
    scan_part_kernel<<<sb, 256>>>(N);
    scan_final_kernel<<<sb, 1024>>>(N, sb);
    fill_kernel<<<eb, 256>>>(src, dst, E);
    transpose_w_kernel<<<dim3(4, 4, 5), dim3(32, 8)>>>(W1, W2, W3, Wt1, Wt2);

    const float* w1t = pwt + 0 * D * D;
    const float* w2t = pwt + 1 * D * D;
    const float* w3t = pwt + 2 * D * D;
    const float* wt1t = pwt + 3 * D * D;
    const float* wt2t = pwt + 4 * D * D;

    // layer 1
    gemm_kernel<<<gg, 256, SMEM>>>(ent, w1t, nullptr, nullptr, nullptr, ph16, N, 3);
    agg_ln_kernel<<<ab, 256>>>(ph16, b1, g1, be1, px, N, 1);
    // layer 2
    gemm_kernel<<<gg, 256, SMEM>>>(px, w2t, nullptr, nullptr, nullptr, ph16, N, 3);
    agg_ln_kernel<<<ab, 256>>>(ph16, b2, g2, be2, py, N, 1);
    // layer 3 (LN, no relu)
    gemm_kernel<<<gg, 256, SMEM>>>(py, w3t, nullptr, nullptr, nullptr, ph16, N, 3);
    agg_ln_kernel<<<ab, 256>>>(ph16, b3, g3, be3, px, N, 0);
    // transform MLP + residual with x0
    gemm_kernel<<<gg, 256, SMEM>>>(px, wt1t, bt1, nullptr, py, nullptr, N, 1);
    gemm_kernel<<<gg, 256, SMEM>>>(py, wt2t, bt2, ent, (float*)d_out, nullptr, N, 2);
}

// round 10
// speedup vs baseline: 1.1596x; 1.1596x over previous
#include <cuda_runtime.h>
#include <cuda_fp16.h>

#define D 128
#define DV 32            // float4 per row
#define BM 64            // gemm rows per block
#define MAXN 100352
#define MAXE 1700000

// ---------------- scratch (device globals: no allocation allowed) -------------
__device__ unsigned g_h16[MAXN * 64];   // half2-packed pre-scaled hidden (25.7MB)
__device__ float g_x[MAXN * D];
__device__ float g_y[MAXN * D];
__device__ float g_dinv[MAXN];
__device__ int   g_deg[MAXN];
__device__ int   g_rowstart[MAXN + 1];
__device__ int   g_cursor[MAXN];
__device__ int   g_csr_src[MAXE];
__device__ int   g_part[64];

// ---------------- packed f32x2 helpers (Blackwell FFMA2 path) ----------------
__device__ __forceinline__ unsigned long long pack2(float a, float b) {
    unsigned long long r;
    asm("mov.b64 %0, {%1, %2};" : "=l"(r) : "f"(a), "f"(b));
    return r;
}
__device__ __forceinline__ void unpack2(unsigned long long v, float& a, float& b) {
    asm("mov.b64 {%0, %1}, %2;" : "=f"(a), "=f"(b) : "l"(v));
}
__device__ __forceinline__ unsigned long long ffma2(unsigned long long a,
                                                    unsigned long long b,
                                                    unsigned long long c) {
    unsigned long long d;
    asm("fma.rn.f32x2 %0, %1, %2, %3;" : "=l"(d) : "l"(a), "l"(b), "l"(c));
    return d;
}

// ---------------- degree / normalization ------------------------------------
__global__ void zero_deg_kernel(int n) {
    int i = blockIdx.x * blockDim.x + threadIdx.x;
    if (i < n) g_deg[i] = 0;
}

__global__ void count_deg_kernel(const int* __restrict__ dst, int E) {
    int e = blockIdx.x * blockDim.x + threadIdx.x;
    if (e < E) atomicAdd(&g_deg[dst[e]], 1);
}

__global__ void dinv_kernel(int n) {
    int i = blockIdx.x * blockDim.x + threadIdx.x;
    if (i < n) g_dinv[i] = rsqrtf((float)(g_deg[i] + 1));
}

// ---- multi-block scan: pass 1, per-block (4096 elems) partial sums ----------
__global__ void scan_part_kernel(int n) {
    int base = blockIdx.x * 4096;
    int sum = 0;
    for (int i = threadIdx.x; i < 4096; i += 256) {
        int idx = base + i;
        if (idx < n) sum += g_deg[idx];
    }
    #pragma unroll
    for (int o = 16; o > 0; o >>= 1) sum += __shfl_xor_sync(0xffffffffu, sum, o);
    __shared__ int ws[8];
    if ((threadIdx.x & 31) == 0) ws[threadIdx.x >> 5] = sum;
    __syncthreads();
    if (threadIdx.x == 0) {
        int t = 0;
        #pragma unroll
        for (int w = 0; w < 8; ++w) t += ws[w];
        g_part[blockIdx.x] = t;
    }
}

// ---- pass 2: per-block exclusive scan of its 4096 chunk + global offset -----
__global__ void scan_final_kernel(int n, int nblocks) {
    __shared__ int s_off;
    __shared__ int warp_sums[32];
    int tid = threadIdx.x;                  // 1024 threads
    int base = blockIdx.x * 4096;
    if (tid == 0) {
        int off = 0;
        for (int b = 0; b < blockIdx.x; ++b) off += g_part[b];
        s_off = off;
        if (blockIdx.x == 0) {
            int tot = 0;
            for (int b = 0; b < nblocks; ++b) tot += g_part[b];
            g_rowstart[n] = tot;
        }
    }
    __syncthreads();

    int i0 = base + tid * 4;
    int v[4];
    int s = 0;
    #pragma unroll
    for (int k = 0; k < 4; ++k) {
        int idx = i0 + k;
        v[k] = (idx < n) ? g_deg[idx] : 0;
        s += v[k];
    }
    int lane = tid & 31, wid = tid >> 5;
    int x = s;
    #pragma unroll
    for (int o = 1; o < 32; o <<= 1) {
        int y = __shfl_up_sync(0xffffffffu, x, o);
        if (lane >= o) x += y;
    }
    if (lane == 31) warp_sums[wid] = x;
    __syncthreads();
    if (wid == 0) {
        int w = warp_sums[lane];
        #pragma unroll
        for (int o = 1; o < 32; o <<= 1) {
            int y = __shfl_up_sync(0xffffffffu, w, o);
            if (lane >= o) w += y;
        }
        warp_sums[lane] = w;
    }
    __syncthreads();
    int excl = x - s + ((wid > 0) ? warp_sums[wid - 1] : 0) + s_off;
    #pragma unroll
    for (int k = 0; k < 4; ++k) {
        int idx = i0 + k;
        if (idx < n) {
            g_rowstart[idx] = excl;
            g_cursor[idx]   = excl;
            excl += v[k];
        }
    }
}

__global__ void fill_kernel(const int* __restrict__ src, const int* __restrict__ dst, int E) {
    int e = blockIdx.x * blockDim.x + threadIdx.x;
    if (e >= E) return;
    int u = src[e], v = dst[e];
    int slot = atomicAdd(&g_cursor[v], 1);
    g_csr_src[slot] = u;
}

// ---------------- GEMM: out = X @ W (+epilogues), packed f32x2 FMA -----------
// epi: 1 = relu(acc + bias) -> fp32 out; 2 = acc + bias + add[row] -> fp32 out
// epi: 3 = write half2( dinv[row] * acc ) into h16 buffer (pre-scaled gather payload)
__global__ void gemm_kernel(const float* __restrict__ X, const float* __restrict__ W,
                            const float* __restrict__ bias, const float* __restrict__ add,
                            float* __restrict__ out, unsigned* __restrict__ out16,
                            int M, int epi) {
    extern __shared__ float sm[];
    float* Ws = sm;              // 128*128
    float* Xs = sm + D * D;      // BM*128
    int row0 = blockIdx.x * BM;

    // load full W (64KB)
    const float4* W4 = (const float4*)W;
    float4* Ws4w = (float4*)Ws;
    for (int i = threadIdx.x; i < D * D / 4; i += 256) Ws4w[i] = W4[i];

    // load X tile (guard rows)
    const float4* X4 = (const float4*)X;
    float4* Xs4 = (float4*)Xs;
    for (int i = threadIdx.x; i < BM * D / 4; i += 256) {
        int r = i >> 5;           // 32 float4 per row
        int c = i & 31;
        int gr = row0 + r;
        float4 v = make_float4(0.f, 0.f, 0.f, 0.f);
        if (gr < M) v = X4[gr * DV + c];
        Xs4[i] = v;
    }
    __syncthreads();

    int tx = threadIdx.x & 31;    // cols 4*tx .. 4*tx+3
    int ty = threadIdx.x >> 5;    // rows ty*8 .. ty*8+7

    unsigned long long acc2[8][2];
    #pragma unroll
    for (int r = 0; r < 8; ++r) { acc2[r][0] = 0ull; acc2[r][1] = 0ull; }

    const float4* Ws4 = (const float4*)Ws;
    const float* Xrow = Xs + (ty * 8) * D;

    #pragma unroll 4
    for (int k = 0; k < D; ++k) {
        float4 w = Ws4[k * DV + tx];
        unsigned long long wxy = pack2(w.x, w.y);
        unsigned long long wzw = pack2(w.z, w.w);
        #pragma unroll
        for (int r = 0; r < 8; ++r) {
            float xv = Xrow[r * D + k];
            unsigned long long xx = pack2(xv, xv);
            acc2[r][0] = ffma2(xx, wxy, acc2[r][0]);
            acc2[r][1] = ffma2(xx, wzw, acc2[r][1]);
        }
    }

    if (epi == 3) {
        // pre-scaled fp16 output: hs[row] = dinv[row] * acc
        #pragma unroll
        for (int r = 0; r < 8; ++r) {
            int gr = row0 + ty * 8 + r;
            if (gr >= M) continue;
            float s = g_dinv[gr];
            float4 o;
            unpack2(acc2[r][0], o.x, o.y);
            unpack2(acc2[r][1], o.z, o.w);
            __half2 h0 = __floats2half2_rn(o.x * s, o.y * s);
            __half2 h1 = __floats2half2_rn(o.z * s, o.w * s);
            uint2 pk = make_uint2(*(unsigned*)&h0, *(unsigned*)&h1);
            *(uint2*)(out16 + gr * 64 + 2 * tx) = pk;
        }
        return;
    }

    float4 bv = ((const float4*)bias)[tx];
    float4* out4 = (float4*)out;
    const float4* add4 = (const float4*)add;

    #pragma unroll
    for (int r = 0; r < 8; ++r) {
        int gr = row0 + ty * 8 + r;
        if (gr >= M) continue;
        float4 o;
        unpack2(acc2[r][0], o.x, o.y);
        unpack2(acc2[r][1], o.z, o.w);
        o.x += bv.x; o.y += bv.y; o.z += bv.z; o.w += bv.w;
        if (epi == 1) {
            o.x = fmaxf(o.x, 0.f); o.y = fmaxf(o.y, 0.f);
            o.z = fmaxf(o.z, 0.f); o.w = fmaxf(o.w, 0.f);
        } else {
            float4 a = add4[gr * DV + tx];
            o.x += a.x; o.y += a.y; o.z += a.z; o.w += a.w;
        }
        out4[gr * DV + tx] = o;
    }
}

// ---------------- fused aggregation + bias + LayerNorm (+ReLU) ---------------
// warp per node, fp16 pre-scaled payload, 4-way unrolled gather (MLP=4):
// out[v] = LN( dinv[v] * ( hs[v] + sum_{u->v} hs[u] ) + bias )
__device__ __forceinline__ void acc_payload(float4& acc, const unsigned* __restrict__ h16,
                                            int u, int lane) {
    uint2 p = *(const uint2*)(h16 + u * 64 + 2 * lane);
    float2 a = __half22float2(*(__half2*)&p.x);
    float2 b = __half22float2(*(__half2*)&p.y);
    acc.x += a.x; acc.y += a.y; acc.z += b.x; acc.w += b.y;
}

__global__ void agg_ln_kernel(const unsigned* __restrict__ h16,
                              const float* __restrict__ bias,
                              const float* __restrict__ gamma, const float* __restrict__ beta,
                              float* __restrict__ out, int N, int doRelu) {
    int gw   = (blockIdx.x * blockDim.x + threadIdx.x) >> 5;
    int lane = threadIdx.x & 31;
    if (gw >= N) return;
    int v = gw;

    // self term -> acc0; three more independent accumulators for MLP
    uint2 pk = *(const uint2*)(h16 + v * 64 + 2 * lane);
    float2 f0 = __half22float2(*(__half2*)&pk.x);
    float2 f1 = __half22float2(*(__half2*)&pk.y);
    float4 acc0 = make_float4(f0.x, f0.y, f1.x, f1.y);
    float4 acc1 = make_float4(0.f, 0.f, 0.f, 0.f);
    float4 acc2 = make_float4(0.f, 0.f, 0.f, 0.f);
    float4 acc3 = make_float4(0.f, 0.f, 0.f, 0.f);

    int s = g_rowstart[v];
    int e = g_rowstart[v + 1];
    int j = s;
    for (; j + 4 <= e; j += 4) {
        int u0 = g_csr_src[j];
        int u1 = g_csr_src[j + 1];
        int u2 = g_csr_src[j + 2];
        int u3 = g_csr_src[j + 3];
        acc_payload(acc0, h16, u0, lane);
        acc_payload(acc1, h16, u1, lane);
        acc_payload(acc2, h16, u2, lane);
        acc_payload(acc3, h16, u3, lane);
    }
    for (; j < e; ++j) {
        int u = g_csr_src[j];
        acc_payload(acc0, h16, u, lane);
    }
    float4 acc;
    acc.x = (acc0.x + acc1.x) + (acc2.x + acc3.x);
    acc.y = (acc0.y + acc1.y) + (acc2.y + acc3.y);
    acc.z = (acc0.z + acc1.z) + (acc2.z + acc3.z);
    acc.w = (acc0.w + acc1.w) + (acc2.w + acc3.w);

    float dv = g_dinv[v];
    float4 bv = ((const float4*)bias)[lane];
    acc.x = acc.x * dv + bv.x;
    acc.y = acc.y * dv + bv.y;
    acc.z = acc.z * dv + bv.z;
    acc.w = acc.w * dv + bv.w;

    // mean over 128
    float sum = acc.x + acc.y + acc.z + acc.w;
    #pragma unroll
    for (int o = 16; o > 0; o >>= 1) sum += __shfl_xor_sync(0xffffffffu, sum, o);
    float mu = sum * (1.0f / 128.0f);

    float cx = acc.x - mu, cy = acc.y - mu, cz = acc.z - mu, cw = acc.w - mu;
    float sq = cx * cx + cy * cy + cz * cz + cw * cw;
    #pragma unroll
    for (int o = 16; o > 0; o >>= 1) sq += __shfl_xor_sync(0xffffffffu, sq, o);
    float rs = rsqrtf(sq * (1.0f / 128.0f) + 1e-5f);

    float4 gv  = ((const float4*)gamma)[lane];
    float4 bev = ((const float4*)beta)[lane];
    float4 o;
    o.x = cx * rs * gv.x + bev.x;
    o.y = cy * rs * gv.y + bev.y;
    o.z = cz * rs * gv.z + bev.z;
    o.w = cw * rs * gv.w + bev.w;
    if (doRelu) {
        o.x = fmaxf(o.x, 0.f); o.y = fmaxf(o.y, 0.f);
        o.z = fmaxf(o.z, 0.f); o.w = fmaxf(o.w, 0.f);
    }
    ((float4*)out)[v * DV + lane] = o;
}

// ---------------- driver -----------------------------------------------------
extern "C" void kernel_launch(void* const* d_in, const int* in_sizes, int n_in,
                              void* d_out, int out_size) {
    const int*   edge_index = (const int*)d_in[0];
    const float* ent = (const float*)d_in[1];
    const float* W1  = (const float*)d_in[2];
    const float* b1  = (const float*)d_in[3];
    const float* g1  = (const float*)d_in[4];
    const float* be1 = (const float*)d_in[5];
    const float* W2  = (const float*)d_in[6];
    const float* b2  = (const float*)d_in[7];
    const float* g2  = (const float*)d_in[8];
    const float* be2 = (const float*)d_in[9];
    const float* W3  = (const float*)d_in[10];
    const float* b3  = (const float*)d_in[11];
    const float* g3  = (const float*)d_in[12];
    const float* be3 = (const float*)d_in[13];
    const float* Wt1 = (const float*)d_in[14];
    const float* bt1 = (const float*)d_in[15];
    const float* Wt2 = (const float*)d_in[16];
    const float* bt2 = (const float*)d_in[17];

    int E = in_sizes[0] / 2;
    int N = in_sizes[1] / D;
    const int* src = edge_index;
    const int* dst = edge_index + E;

    float *px, *py;
    unsigned *ph16;
    cudaGetSymbolAddress((void**)&ph16, g_h16);
    cudaGetSymbolAddress((void**)&px, g_x);
    cudaGetSymbolAddress((void**)&py, g_y);

    const int SMEM = (D * D + BM * D) * sizeof(float);   // 96 KB
    cudaFuncSetAttribute(gemm_kernel, cudaFuncAttributeMaxDynamicSharedMemorySize, SMEM);

    int nb  = (N + 255) / 256;
    int eb  = (E + 255) / 256;
    int gg  = (N + BM - 1) / BM;
    int ab  = (N * 32 + 255) / 256;
    int sb  = (N + 4095) / 4096;

    // graph preprocessing (CSR by dst, symmetric normalization)
    zero_deg_kernel<<<nb, 256>>>(N);
    count_deg_kernel<<<eb, 256>>>(dst, E);
    dinv_kernel<<<nb, 256>>>(N);
    scan_part_kernel<<<sb, 256>>>(N);
    scan_final_kernel<<<sb, 1024>>>(N, sb);
    fill_kernel<<<eb, 256>>>(src, dst, E);

    // layer 1
    gemm_kernel<<<gg, 256, SMEM>>>(ent, W1, nullptr, nullptr, nullptr, ph16, N, 3);
    agg_ln_kernel<<<ab, 256>>>(ph16, b1, g1, be1, px, N, 1);
    // layer 2
    gemm_kernel<<<gg, 256, SMEM>>>(px, W2, nullptr, nullptr, nullptr, ph16, N, 3);
    agg_ln_kernel<<<ab, 256>>>(ph16, b2, g2, be2, py, N, 1);
    // layer 3 (LN, no relu)
    gemm_kernel<<<gg, 256, SMEM>>>(py, W3, nullptr, nullptr, nullptr, ph16, N, 3);
    agg_ln_kernel<<<ab, 256>>>(ph16, b3, g3, be3, px, N, 0);
    // transform MLP + residual with x0
    gemm_kernel<<<gg, 256, SMEM>>>(px, Wt1, bt1, nullptr, py, nullptr, N, 1);
    gemm_kernel<<<gg, 256, SMEM>>>(py, Wt2, bt2, ent, (float*)d_out, nullptr, N, 2);
}